// round 17
// baseline (speedup 1.0000x reference)
#include <cuda_runtime.h>

#define T 512
#define C 6
#define R 256
#define BC 2
#define NBLK 128        // 128 CTAs x 2 batches, one wave
#define NRPP 22         // reg k-pairs per warp (44 of its 64 k-rows)
#define NSPP 10         // smem k-pairs per warp (20 rows)
#define WSM_ULL (4 * NSPP * 256)   // 40 pair-rows x 256 r = 80KB
#define REDN (4 * 2 * R)           // one red buffer: 4 k-slices x (2 floats per r)

typedef unsigned long long ull;

// Packed 2xfp32 FMA (sm_100+): d.lane += a.lane * b.lane
__device__ __forceinline__ void fma2(ull& d, ull a, ull b) {
    asm("fma.rn.f32x2 %0, %1, %2, %0;" : "+l"(d) : "l"(a), "l"(b));
}
__device__ __forceinline__ float sum2(ull a) {
    float lo, hi;
    asm("mov.b64 {%0,%1}, %2;" : "=f"(lo), "=f"(hi) : "l"(a));
    return lo + hi;
}
__device__ __forceinline__ ull pack2(float lo, float hi) {
    ull u; asm("mov.b64 %0, {%1,%2};" : "=l"(u) : "f"(lo), "f"(hi));
    return u;
}
// tanh(z) = 1 - 2/(exp(2z)+1): exp->inf gives exactly 1 (no NaN); abs err ~1e-7.
__device__ __forceinline__ float tanh_fast(float z) {
    float e = __expf(2.0f * z);
    return 1.0f - __fdividef(2.0f, e + 1.0f);
}

// Fan-in-4 split (k x r warp tiling):
//   warp w = 2i + p: k-slice i -> k in [64i, 64i+64) (= local k-pairs 0..31),
//                    r-half p  -> r in [128p, 128p+128)
//     local pairs 0..21  -> registers (wreg: 22 pairs x 4 r = 88 ull = 176 regs)
//     local pairs 22..31 -> smem Wsm (20 rows/warp-slice: 80KB -> 640 wf/step)
//   lane l owns r(g,s) = 128p + 64g + 2l + s  (g=0..1, s=0..1 -> 4 outputs x 2 b)
//   Reduction fan-in = 4 (was 8): red traffic and phase2 adds halve.
//   h[64i..64i+64) is produced by threads 64i..64i+64 = warps {2i, 2i+1} and
//   consumed ONLY by those warps -> pair-local named barrier (bar.sync 1+i, 64)
//   instead of a second block barrier. ONE __syncthreads per step (red).
// smem: Wsm 80KB | hsm 2KB | red x2 16KB | xsm 24KB = 122KB
__global__ void __launch_bounds__(256, 1)
esn_kernel(const float* __restrict__ x, const float* __restrict__ W_in,
           const float* __restrict__ W_res, float* __restrict__ out)
{
    extern __shared__ char smraw[];
    ull*   Wsm  = (ull*)smraw;
    float* hsm  = (float*)(Wsm + WSM_ULL);
    float* red0 = hsm + 2 * R;
    float* red1 = red0 + REDN;
    float* xsm  = red1 + REDN;            // [b(2)][t(512)][c(6)]

    const int tid = threadIdx.x;
    const int w = tid >> 5, l = tid & 31;
    const int i = w >> 1, p = w & 1;
    const int b0 = blockIdx.x * BC;

    // Stage x for both batches (contiguous, float4-coalesced).
    {
        const float4* xg = (const float4*)(x + (size_t)b0 * T * C);
        float4* xs = (float4*)xsm;
        for (int m = tid; m < (BC * T * C) / 4; m += 256) xs[m] = xg[m];
    }
    // Stage smem W part: row = i*NSPP + sp holds pair (k0, k0+1), k0 = 64i + 2*NRPP + 2*sp.
    // Wsm[row][r] = (W[k0][r], W[k0+1][r]).  Coalesced gmem reads (r = tid).
    for (int row = 0; row < 4 * NSPP; ++row) {
        int ii = row / NSPP, sp = row % NSPP;
        int k0 = 64 * ii + 2 * NRPP + 2 * sp;
        Wsm[row * R + tid] = pack2(W_res[k0 * R + tid], W_res[(k0 + 1) * R + tid]);
    }
    // Register part: local pairs pl=0..21 -> k0 = 64i + 2*pl; this thread's 4 r's.
    ull wreg[NRPP * 4];
    #pragma unroll
    for (int pl = 0; pl < NRPP; ++pl) {
        int k0 = 64 * i + 2 * pl;
        #pragma unroll
        for (int g = 0; g < 2; ++g) {
            int r0 = 128 * p + 64 * g + 2 * l;
            wreg[pl * 4 + 2 * g + 0] = pack2(W_res[k0 * R + r0],     W_res[(k0 + 1) * R + r0]);
            wreg[pl * 4 + 2 * g + 1] = pack2(W_res[k0 * R + r0 + 1], W_res[(k0 + 1) * R + r0 + 1]);
        }
    }
    float win[C];
    #pragma unroll
    for (int c = 0; c < C; ++c) win[c] = W_in[c * R + tid];

    hsm[tid] = 0.0f; hsm[R + tid] = 0.0f;
    __syncthreads();

    // Warp-uniform h slice pointers (broadcast LDS, 1 wf each); 16 chunks cover 64 k.
    const ulonglong2* hp0 = (const ulonglong2*)(hsm + 64 * i);
    const ulonglong2* hp1 = (const ulonglong2*)(hsm + R + 64 * i);
    const ull* Wb = Wsm + (size_t)i * NSPP * R;      // this slice's smem rows
    const float2* xv0 = (const float2*)(xsm);             // batch b0
    const float2* xv1 = (const float2*)(xsm + T * C);     // batch b0+1
    float* __restrict__ o0 = out + (size_t)b0 * T * R + tid;
    float* __restrict__ o1 = out + (size_t)(b0 + 1) * T * R + tid;
    const int pairbar = 1 + (tid >> 6);   // named barrier id per warp-pair (1..4)

    for (int t = 0; t < T; ++t) {
        float* redc = (t & 1) ? red1 : red0;   // ping-pong partials buffer

        // x loads + xp early (latency hidden; only xp0/xp1 live across the bar).
        float2 xa = xv0[3 * t], xb = xv0[3 * t + 1], xc = xv0[3 * t + 2];
        float2 xd = xv1[3 * t], xe = xv1[3 * t + 1], xf = xv1[3 * t + 2];
        float xp0 = xa.x * win[0] + xa.y * win[1] + xb.x * win[2]
                  + xb.y * win[3] + xc.x * win[4] + xc.y * win[5];
        float xp1 = xd.x * win[0] + xd.y * win[1] + xe.x * win[2]
                  + xe.y * win[3] + xf.x * win[4] + xf.y * win[5];

        // acc[(2g+s)*2 + b]: lanes carry (even-k, odd-k) partials for r(g,s), batch b.
        ull acc[8];
        #pragma unroll
        for (int a = 0; a < 8; ++a) acc[a] = 0;

        // ---- register part: local pairs 0..21 = h chunks q=0..10
        #pragma unroll
        for (int q = 0; q < 11; ++q) {
            ulonglong2 ha = hp0[q];
            ulonglong2 hb = hp1[q];
            #pragma unroll
            for (int gs = 0; gs < 4; ++gs) {
                fma2(acc[gs * 2 + 0], ha.x, wreg[(2 * q) * 4 + gs]);
                fma2(acc[gs * 2 + 1], hb.x, wreg[(2 * q) * 4 + gs]);
                fma2(acc[gs * 2 + 0], ha.y, wreg[(2 * q + 1) * 4 + gs]);
                fma2(acc[gs * 2 + 1], hb.y, wreg[(2 * q + 1) * 4 + gs]);
            }
        }
        // ---- smem part: h chunks q=11..15 (local smem pairs 0..9), LDS.128 16B-stride
        #pragma unroll
        for (int q = 11; q < 16; ++q) {
            const int sp0 = 2 * (q - 11), sp1 = sp0 + 1;
            ulonglong2 ha = hp0[q];
            ulonglong2 hb = hp1[q];
            #pragma unroll
            for (int g = 0; g < 2; ++g) {
                const int r0 = 128 * p + 64 * g + 2 * l;
                ulonglong2 wA = *(const ulonglong2*)(Wb + sp0 * R + r0); // (r0, r0+1), pair sp0
                ulonglong2 wB = *(const ulonglong2*)(Wb + sp1 * R + r0); // (r0, r0+1), pair sp1
                fma2(acc[(2 * g + 0) * 2 + 0], ha.x, wA.x);
                fma2(acc[(2 * g + 1) * 2 + 0], ha.x, wA.y);
                fma2(acc[(2 * g + 0) * 2 + 1], hb.x, wA.x);
                fma2(acc[(2 * g + 1) * 2 + 1], hb.x, wA.y);
                fma2(acc[(2 * g + 0) * 2 + 0], ha.y, wB.x);
                fma2(acc[(2 * g + 1) * 2 + 0], ha.y, wB.y);
                fma2(acc[(2 * g + 0) * 2 + 1], hb.y, wB.x);
                fma2(acc[(2 * g + 1) * 2 + 1], hb.y, wB.y);
            }
        }

        // Publish partials: redc[i][2r + b], float4 per g (16B-stride, conflict-free).
        #pragma unroll
        for (int g = 0; g < 2; ++g) {
            int r0 = 128 * p + 64 * g + 2 * l;
            float4 v;
            v.x = sum2(acc[(2 * g + 0) * 2 + 0]);
            v.y = sum2(acc[(2 * g + 0) * 2 + 1]);
            v.z = sum2(acc[(2 * g + 1) * 2 + 0]);
            v.w = sum2(acc[(2 * g + 1) * 2 + 1]);
            *(float4*)&redc[i * 2 * R + 2 * r0] = v;
        }

        __syncthreads();   // partials STS -> phase2 LDS (single block bar per step)

        // ---- phase2: thread tid = r; reduce 4 k-slices' partials (fan-in 4).
        const float2* rp = (const float2*)&redc[2 * tid];
        float2 q0 = rp[0 * R], q1 = rp[1 * R], q2 = rp[2 * R], q3 = rp[3 * R];
        float sx = (q0.x + q1.x) + (q2.x + q3.x);
        float sy = (q0.y + q1.y) + (q2.y + q3.y);

        float h0n = tanh_fast(sx + xp0);
        float h1n = tanh_fast(sy + xp1);

        hsm[tid]     = h0n;        // consumed next step only by this thread's warp-PAIR
        hsm[R + tid] = h1n;
        o0[(size_t)t * R] = h0n;   // coalesced STG
        o1[(size_t)t * R] = h1n;

        // Pair-local named barrier: h producers == consumers == threads of this
        // 64-thread pair; orders h STS -> next step's broadcast LDS without a
        // second block-wide barrier.
        asm volatile("bar.sync %0, %1;" :: "r"(pairbar), "r"(64) : "memory");
    }
}

extern "C" void kernel_launch(void* const* d_in, const int* in_sizes, int n_in,
                              void* d_out, int out_size) {
    const float* x     = (const float*)d_in[0];
    const float* W_in  = (const float*)d_in[1];
    const float* W_res = (const float*)d_in[2];
    float* out = (float*)d_out;

    // 80KB (Wsm) + 2KB (hsm) + 16KB (red x2) + 24KB (xsm) = 124928 bytes
    const size_t smem_bytes = (size_t)WSM_ULL * sizeof(ull)
                            + (size_t)2 * R * sizeof(float)
                            + (size_t)2 * REDN * sizeof(float)
                            + (size_t)BC * T * C * sizeof(float);
    cudaFuncSetAttribute(esn_kernel, cudaFuncAttributeMaxDynamicSharedMemorySize,
                         (int)smem_bytes);
    esn_kernel<<<NBLK, R, smem_bytes>>>(x, W_in, W_res, out);
}